// round 10
// baseline (speedup 1.0000x reference)
#include <cuda_runtime.h>
#include <cuda_fp16.h>

typedef unsigned int u32;
typedef unsigned long long u64;

#define RANKS 4
#define OCN   128
#define ICN   128
#define HH    56
#define WW    56
#define HW    3136
#define NST   24                      // stages per tile (48 k each)
#define KPST  24                      // kpairs per stage
#define NTILES 1792
#define NCTA   148

#define B_STAGE_W (KPST*512)          // 12288 words = 49152 B
#define B_STAGE_BYTES 49152
#define AP    28                      // A row stride in words (bank-exhaustive for frag loads)
#define A_BUF_BYTES (64*AP*4)         // 7168

#define SM_B0 1024
#define SM_A0 (1024 + 3*B_STAGE_BYTES)         // 148480
#define SM_A1 (SM_A0 + A_BUF_BYTES)            // 155648
#define SM_PART (SM_A1 + A_BUF_BYTES)          // 162816
#define SM_TOTAL (SM_PART + 64*132*4)          // 196608

__device__ __align__(16) u32   g_wB[NST * B_STAGE_W];  // fp16x2, pre-swizzled smem image
__device__ __align__(16) float g_cw[RANKS * HW];       // softmax combine weights

// ---------------- helpers ----------------
__device__ __forceinline__ u32 smem_u32(const void* p) {
    u32 a;
    asm("{ .reg .u64 t; cvta.to.shared.u64 t, %1; cvt.u32.u64 %0, t; }" : "=r"(a) : "l"(p));
    return a;
}
__device__ __forceinline__ u32 pack_h2(float lo, float hi) {
    __half2 h = __floats2half2_rn(lo, hi);
    return *(u32*)&h;
}
__device__ __forceinline__ void mbar_init(u32 addr, u32 cnt) {
    asm volatile("mbarrier.init.shared.b64 [%0], %1;" :: "r"(addr), "r"(cnt) : "memory");
}
__device__ __forceinline__ void mbar_expect_tx(u32 addr, u32 bytes) {
    asm volatile("mbarrier.arrive.expect_tx.shared.b64 _, [%0], %1;" :: "r"(addr), "r"(bytes) : "memory");
}
__device__ __forceinline__ void mbar_wait(u32 addr, int phase) {
    asm volatile(
        "{\n\t.reg .pred P;\n"
        "WL_%=:\n\t"
        "mbarrier.try_wait.parity.acquire.cta.shared::cta.b64 P, [%0], %1, 0x989680;\n\t"
        "@P bra.uni WD_%=;\n\t"
        "bra.uni WL_%=;\n\t"
        "WD_%=:\n\t}"
        :: "r"(addr), "r"((u32)phase) : "memory");
}
__device__ __forceinline__ void bulk_copy(u32 dst, const void* src, u32 bytes, u32 mbar) {
    asm volatile(
        "cp.async.bulk.shared::cluster.global.mbarrier::complete_tx::bytes [%0], [%1], %2, [%3];"
        :: "r"(dst), "l"(src), "r"(bytes), "r"(mbar) : "memory");
}
__device__ __forceinline__ void mma_f16(float& d0, float& d1, float& d2, float& d3,
                                        u32 a0, u32 a1, u32 a2, u32 a3, u32 b0, u32 b1) {
    asm volatile(
        "mma.sync.aligned.m16n8k16.row.col.f32.f16.f16.f32 "
        "{%0,%1,%2,%3}, {%4,%5,%6,%7}, {%8,%9}, {%0,%1,%2,%3};"
        : "+f"(d0), "+f"(d1), "+f"(d2), "+f"(d3)
        : "r"(a0), "r"(a1), "r"(a2), "r"(a3), "r"(b0), "r"(b1));
}

// ---------------- prep kernels ----------------
__global__ void prep_cw_kernel(const float* __restrict__ cw_row,
                               const float* __restrict__ cw_col) {
    int idx = blockIdx.x * blockDim.x + threadIdx.x;
    if (idx >= HW) return;
    int y = idx / WW, x = idx % WW;
    float v0 = cw_row[0 * HH + y] + cw_col[0 * WW + x];
    float v1 = cw_row[1 * HH + y] + cw_col[1 * WW + x];
    float v2 = cw_row[2 * HH + y] + cw_col[2 * WW + x];
    float v3 = cw_row[3 * HH + y] + cw_col[3 * WW + x];
    float m = fmaxf(fmaxf(v0, v1), fmaxf(v2, v3));
    float e0 = expf(v0 - m), e1 = expf(v1 - m), e2 = expf(v2 - m), e3 = expf(v3 - m);
    float inv = 1.0f / (e0 + e1 + e2 + e3);
    g_cw[0 * HW + idx] = e0 * inv;
    g_cw[1 * HW + idx] = e1 * inv;
    g_cw[2 * HW + idx] = e2 * inv;
    g_cw[3 * HW + idx] = e3 * inv;
}

// Weights -> fp16 pairs in swizzled smem image.
// Global k = s*48 + 2*kp + {0,1}; tap = k>>7, ic = k&127 (pair shares tap).
// smem word (kp, n): kp*512 + (n ^ ((kp&3)<<3)),  n = rank*128 + oc.
__global__ void prep_wB_kernel(const float* __restrict__ w) {
    int idx = blockIdx.x * blockDim.x + threadIdx.x;
    if (idx >= NST * B_STAGE_W) return;
    int n  = idx & 511;
    int kp = (idx >> 9) % KPST;
    int s  = idx / (512 * KPST);
    int r  = n >> 7, oc = n & 127;
    int k0 = s * 48 + 2 * kp;
    int tap = k0 >> 7;
    int ic  = k0 & 127;
    const float* wp = w + (((size_t)r * OCN + oc) * ICN + ic) * 9 + tap;
    g_wB[(size_t)s * B_STAGE_W + kp * 512 + (n ^ ((kp & 3) << 3))] = pack_h2(wp[0], wp[9]);
}

// ---------------- A staging (im2col, per-kpair tap decode) ----------------
__device__ __forceinline__ void ldgA(float* av, const float* __restrict__ x,
                                     int bb, int y, int s, int px, int kpb) {
#pragma unroll
    for (int j = 0; j < 6; j++) {
        const int kp = kpb + j * 4;
        const int k0 = s * 48 + 2 * kp;
        const int tap = k0 >> 7;
        const int ic  = k0 & 127;
        const int gy = y + tap / 3 - 1;
        const int gx = px + tap % 3 - 1;
        if ((unsigned)gy < 56u && (unsigned)gx < 56u) {
            const float* src = x + (size_t)bb * ICN * HW + (size_t)ic * HW + gy * WW + gx;
            av[2 * j]     = src[0];
            av[2 * j + 1] = src[HW];
        } else {
            av[2 * j] = 0.0f;
            av[2 * j + 1] = 0.0f;
        }
    }
}
__device__ __forceinline__ void stsA(u32* Ab, const float* av, int px, int kpb) {
#pragma unroll
    for (int j = 0; j < 6; j++)
        Ab[px * AP + kpb + j * 4] = pack_h2(av[2 * j], av[2 * j + 1]);
}

// ---------------- main persistent mma kernel ----------------
// grid 148 CTAs x 256 threads; CTA c handles tiles c, c+148, ...
// tile -> bb = tile/56, y = tile%56.  8 warps = 2 warp_m x 4 warp_n(=rank).
// warp: 32 px (two m16 groups) x 128 n.
__global__ __launch_bounds__(256, 1)
void conv_mma_kernel(const float* __restrict__ x, float* __restrict__ out,
                     const float* __restrict__ b_row, const float* __restrict__ b_col,
                     const float* __restrict__ b_ch) {
    extern __shared__ char smem[];
    const u32 sbase = smem_u32(smem);
    const int tid = threadIdx.x;
    const int wid = tid >> 5, lane = tid & 31;
    const int warp_m = wid & 1, warp_n = wid >> 1;
    const int g = lane >> 2, t = lane & 3;
    const int c = blockIdx.x;

    const int ntile = (NTILES - c + NCTA - 1) / NCTA;
    const int total = ntile * NST;

    if (tid == 0) {
        mbar_init(sbase + 0, 1);
        mbar_init(sbase + 8, 1);
        mbar_init(sbase + 16, 1);
    }
    __syncthreads();

    // fragment / staging constants
    const int ar0 = (warp_m * 32 + g) * AP;        // mg0 row g
    const int bcol = warp_n * 128 + g;
    const int txor = t << 3;
    const int apx = tid & 63;
    const int akpb = tid >> 6;                     // 0..3

    float acc[2][16][4];

    // ---- prologue: TMA stages 0,1 ; stageA(0) ----
    if (tid == 0) {
        mbar_expect_tx(sbase + 0, B_STAGE_BYTES);
        bulk_copy(sbase + SM_B0, g_wB, B_STAGE_BYTES, sbase + 0);
        mbar_expect_tx(sbase + 8, B_STAGE_BYTES);
        bulk_copy(sbase + SM_B0 + B_STAGE_BYTES, g_wB + B_STAGE_W, B_STAGE_BYTES, sbase + 8);
    }
    {
        float av[12];
        ldgA(av, x, c / 56, c % 56, 0, apx, akpb);
        stsA((u32*)(smem + SM_A0), av, apx, akpb);
    }

    // ---- main loop over global stages ----
    for (int gs = 0; gs < total; gs++) {
        const int s = gs % NST;
        const int gt = c + (gs / NST) * NCTA;
        const int y = gt % 56, bb = gt / 56;

        mbar_wait(sbase + (gs % 3) * 8, (gs / 3) & 1);
        __syncthreads();

        // prefetch B for gs+2
        if (tid == 0 && gs + 2 < total) {
            const int s2 = (gs + 2) % NST;
            const u32 mb = sbase + ((gs + 2) % 3) * 8;
            mbar_expect_tx(mb, B_STAGE_BYTES);
            bulk_copy(sbase + SM_B0 + ((gs + 2) % 3) * B_STAGE_BYTES,
                      g_wB + (size_t)s2 * B_STAGE_W, B_STAGE_BYTES, mb);
        }

        // early LDG for A(gs+1)
        float av[12];
        const bool doA = (gs + 1 < total);
        if (doA) {
            const int gs1 = gs + 1;
            const int gt1 = c + (gs1 / NST) * NCTA;
            ldgA(av, x, gt1 / 56, gt1 % 56, gs1 % NST, apx, akpb);
        }

        if (s == 0) {
#pragma unroll
            for (int m = 0; m < 2; m++)
#pragma unroll
                for (int i = 0; i < 16; i++)
#pragma unroll
                    for (int j = 0; j < 4; j++) acc[m][i][j] = 0.0f;
        }

        // ---- MMAs for stage gs (48 kc = 3 k16-steps, 2 m16 groups) ----
        const u32* Bb = (const u32*)(smem + SM_B0 + (gs % 3) * B_STAGE_BYTES);
        const u32* Ab = (const u32*)(smem + SM_A0 + (gs & 1) * A_BUF_BYTES);
#pragma unroll
        for (int ks = 0; ks < 3; ks++) {
            const int ak = ks * 8 + t;
            u32 a00 = Ab[ar0 + ak];
            u32 a01 = Ab[ar0 + 8 * AP + ak];
            u32 a02 = Ab[ar0 + ak + 4];
            u32 a03 = Ab[ar0 + 8 * AP + ak + 4];
            u32 a10 = Ab[ar0 + 16 * AP + ak];
            u32 a11 = Ab[ar0 + 24 * AP + ak];
            u32 a12 = Ab[ar0 + 16 * AP + ak + 4];
            u32 a13 = Ab[ar0 + 24 * AP + ak + 4];
            const u32* b0p = Bb + ak * 512 + bcol;
            const u32* b1p = b0p + 4 * 512;
#pragma unroll
            for (int nt = 0; nt < 16; nt++) {
                const int off = (nt << 3) ^ txor;
                const u32 b0 = b0p[off], b1 = b1p[off];
                mma_f16(acc[0][nt][0], acc[0][nt][1], acc[0][nt][2], acc[0][nt][3],
                        a00, a01, a02, a03, b0, b1);
                mma_f16(acc[1][nt][0], acc[1][nt][1], acc[1][nt][2], acc[1][nt][3],
                        a10, a11, a12, a13, b0, b1);
            }
        }

        // store staged A(gs+1)
        if (doA)
            stsA((u32*)(smem + SM_A0 + ((gs + 1) & 1) * A_BUF_BYTES), av, apx, akpb);

        // ---- epilogue at tile end ----
        if (s == NST - 1) {
            __syncthreads();
            float* part = (float*)(smem + SM_PART);
#pragma unroll
            for (int pass = 0; pass < 4; pass++) {
                if (warp_n == pass) {
#pragma unroll
                    for (int mg = 0; mg < 2; mg++) {
                        const int px0 = warp_m * 32 + mg * 16 + g;
                        const int px1 = px0 + 8;
                        const float cw0 = g_cw[warp_n * HW + y * WW + px0];
                        const float cw1 = (px1 < 56) ? g_cw[warp_n * HW + y * WW + px1] : 0.0f;
#pragma unroll
                        for (int nt = 0; nt < 16; nt++) {
                            const int oc = nt * 8 + 2 * t;
                            float* p0 = &part[px0 * 132 + oc];
                            float* p1 = &part[px1 * 132 + oc];
                            if (pass == 0) {
                                p0[0] = cw0 * acc[mg][nt][0]; p0[1] = cw0 * acc[mg][nt][1];
                                p1[0] = cw1 * acc[mg][nt][2]; p1[1] = cw1 * acc[mg][nt][3];
                            } else {
                                p0[0] += cw0 * acc[mg][nt][0]; p0[1] += cw0 * acc[mg][nt][1];
                                p1[0] += cw1 * acc[mg][nt][2]; p1[1] += cw1 * acc[mg][nt][3];
                            }
                        }
                    }
                }
                __syncthreads();
            }
            const float br = b_row[y];
            for (int idx = tid; idx < OCN * 56; idx += 256) {
                const int oc = idx / 56, xx = idx - oc * 56;
                out[((size_t)(bb * OCN + oc) * HH + y) * WW + xx] =
                    part[xx * 132 + oc] + br + b_col[xx] + b_ch[oc];
            }
        }
    }
}

// ---------------- launch ----------------
extern "C" void kernel_launch(void* const* d_in, const int* in_sizes, int n_in,
                              void* d_out, int out_size) {
    const float* x      = (const float*)d_in[0];  // [32,128,56,56]
    const float* w      = (const float*)d_in[1];  // [4,128,128,3,3]
    const float* cw_row = (const float*)d_in[2];  // [4,56,1]
    const float* cw_col = (const float*)d_in[3];  // [4,1,56]
    const float* b_row  = (const float*)d_in[4];  // [1,1,56,1]
    const float* b_col  = (const float*)d_in[5];  // [1,1,1,56]
    const float* b_ch   = (const float*)d_in[6];  // [1,128,1,1]
    float* out = (float*)d_out;

    cudaFuncSetAttribute(conv_mma_kernel,
                         cudaFuncAttributeMaxDynamicSharedMemorySize, SM_TOTAL);

    prep_cw_kernel<<<(HW + 255) / 256, 256>>>(cw_row, cw_col);
    prep_wB_kernel<<<(NST * B_STAGE_W + 255) / 256, 256>>>(w);
    conv_mma_kernel<<<NCTA, 256, SM_TOTAL>>>(x, out, b_row, b_col, b_ch);
}

// round 11
// speedup vs baseline: 1.2665x; 1.2665x over previous
#include <cuda_runtime.h>
#include <cuda_fp16.h>
typedef unsigned int u32;

#define HH 56
#define WW 56
#define HW 3136
#define NSTG 64

#define SM_CWS 64
#define SM_T   4096
#define SM_B   124928
#define SM_A   190464
#define SM_TOTAL 199168

__device__ __align__(16) u32   g_wU[NSTG * 8192];  // [stage][kp64][n128] fp16x2 swizzled
__device__ __align__(16) float g_cw[4 * HW];
__device__ const float CAF[2][4] = {{1.f, 1.f, 1.f, 0.f}, {0.f, 1.f, -1.f, -1.f}};

__device__ __forceinline__ u32 smem_u32(const void* p) {
    u32 a;
    asm("{ .reg .u64 t; cvta.to.shared.u64 t, %1; cvt.u32.u64 %0, t; }" : "=r"(a) : "l"(p));
    return a;
}
__device__ __forceinline__ u32 pack_h2(float lo, float hi) {
    __half2 h = __floats2half2_rn(lo, hi);
    return *(u32*)&h;
}
__device__ __forceinline__ void mbar_init(u32 a, u32 c) {
    asm volatile("mbarrier.init.shared.b64 [%0], %1;" :: "r"(a), "r"(c) : "memory");
}
__device__ __forceinline__ void mbar_expect_tx(u32 a, u32 b) {
    asm volatile("mbarrier.arrive.expect_tx.shared.b64 _, [%0], %1;" :: "r"(a), "r"(b) : "memory");
}
__device__ __forceinline__ void mbar_wait(u32 a, int ph) {
    asm volatile(
        "{\n\t.reg .pred P;\n"
        "WL_%=:\n\t"
        "mbarrier.try_wait.parity.acquire.cta.shared::cta.b64 P, [%0], %1, 0x989680;\n\t"
        "@P bra.uni WD_%=;\n\t"
        "bra.uni WL_%=;\n\t"
        "WD_%=:\n\t}" :: "r"(a), "r"((u32)ph) : "memory");
}
__device__ __forceinline__ void bulk_copy(u32 d, const void* s, u32 b, u32 m) {
    asm volatile(
        "cp.async.bulk.shared::cluster.global.mbarrier::complete_tx::bytes [%0], [%1], %2, [%3];"
        :: "r"(d), "l"(s), "r"(b), "r"(m) : "memory");
}
__device__ __forceinline__ void mma_f16(float& d0, float& d1, float& d2, float& d3,
                                        u32 a0, u32 a1, u32 a2, u32 a3, u32 b0, u32 b1) {
    asm volatile(
        "mma.sync.aligned.m16n8k16.row.col.f32.f16.f16.f32 "
        "{%0,%1,%2,%3}, {%4,%5,%6,%7}, {%8,%9}, {%0,%1,%2,%3};"
        : "+f"(d0), "+f"(d1), "+f"(d2), "+f"(d3)
        : "r"(a0), "r"(a1), "r"(a2), "r"(a3), "r"(b0), "r"(b1));
}

__global__ void prep_cw_kernel(const float* __restrict__ cw_row,
                               const float* __restrict__ cw_col) {
    int idx = blockIdx.x * blockDim.x + threadIdx.x;
    if (idx >= HW) return;
    int y = idx / WW, x = idx % WW;
    float v0 = cw_row[y] + cw_col[x];
    float v1 = cw_row[HH + y] + cw_col[WW + x];
    float v2 = cw_row[2 * HH + y] + cw_col[2 * WW + x];
    float v3 = cw_row[3 * HH + y] + cw_col[3 * WW + x];
    float m = fmaxf(fmaxf(v0, v1), fmaxf(v2, v3));
    float e0 = expf(v0 - m), e1 = expf(v1 - m), e2 = expf(v2 - m), e3 = expf(v3 - m);
    float inv = 1.0f / (e0 + e1 + e2 + e3);
    g_cw[idx] = e0 * inv; g_cw[HW + idx] = e1 * inv;
    g_cw[2 * HW + idx] = e2 * inv; g_cw[3 * HW + idx] = e3 * inv;
}

// U = G w G^T per (rank, oc, ic-pair); stage s = (u*4+v)*4 + r, image [kp][oc^((kp&3)<<3)]
__global__ void prep_wU_kernel(const float* __restrict__ w) {
    int idx = blockIdx.x * blockDim.x + threadIdx.x;
    if (idx >= 4 * 128 * 64) return;
    int kp = idx & 63, oc = (idx >> 6) & 127, r = idx >> 13;
    float U[2][4][4];
#pragma unroll
    for (int e2 = 0; e2 < 2; e2++) {
        const float* wb = w + (((size_t)r * 128 + oc) * 128 + 2 * kp + e2) * 9;
        float tm[4][3];
#pragma unroll
        for (int b = 0; b < 3; b++) {
            float w0 = wb[b], w1 = wb[3 + b], w2 = wb[6 + b];
            tm[0][b] = w0; tm[1][b] = 0.5f * (w0 + w1 + w2);
            tm[2][b] = 0.5f * (w0 - w1 + w2); tm[3][b] = w2;
        }
#pragma unroll
        for (int u = 0; u < 4; u++) {
            U[e2][u][0] = tm[u][0];
            U[e2][u][1] = 0.5f * (tm[u][0] + tm[u][1] + tm[u][2]);
            U[e2][u][2] = 0.5f * (tm[u][0] - tm[u][1] + tm[u][2]);
            U[e2][u][3] = tm[u][2];
        }
    }
    int col = oc ^ ((kp & 3) << 3);
#pragma unroll
    for (int u = 0; u < 4; u++)
#pragma unroll
        for (int v = 0; v < 4; v++)
            g_wU[(size_t)((u * 4 + v) * 4 + r) * 8192 + kp * 128 + col] =
                pack_h2(U[0][u][v], U[1][u][v]);
}

// A_e build: A[b<28][kp] fp16x2 from fp32 T; rows 28-31 stay zero.
__device__ __forceinline__ void buildA(u32* Ab, const float* T, int e, int tid) {
    int u = e >> 2, v = e & 3;
    const float* Tu = T + u * 58 * 130;
#pragma unroll
    for (int it = 0; it < 7; it++) {
        int idx = it * 256 + tid;
        int kp = idx & 63, b = idx >> 6;
        float2 p, q;
        if (v == 0)      { p = *(const float2*)&Tu[(2 * b + 0) * 130 + 2 * kp];
                           q = *(const float2*)&Tu[(2 * b + 2) * 130 + 2 * kp]; }
        else if (v == 1) { p = *(const float2*)&Tu[(2 * b + 1) * 130 + 2 * kp];
                           q = *(const float2*)&Tu[(2 * b + 2) * 130 + 2 * kp]; q.x = -q.x; q.y = -q.y; }
        else if (v == 2) { p = *(const float2*)&Tu[(2 * b + 2) * 130 + 2 * kp];
                           q = *(const float2*)&Tu[(2 * b + 1) * 130 + 2 * kp]; }
        else             { p = *(const float2*)&Tu[(2 * b + 1) * 130 + 2 * kp];
                           q = *(const float2*)&Tu[(2 * b + 3) * 130 + 2 * kp]; }
        Ab[b * 68 + kp] = pack_h2(p.x - q.x, p.y - q.y);
    }
}

// grid (28, 32) = (block-row y0, image). 256 thr = 8 warps (2 wm x 4 woc).
__global__ __launch_bounds__(256, 1)
void wino_kernel(const float* __restrict__ x, float* __restrict__ out,
                 const float* __restrict__ b_row, const float* __restrict__ b_col,
                 const float* __restrict__ b_ch) {
    extern __shared__ char smem[];
    const u32 sbase = smem_u32(smem);
    const int tid = threadIdx.x, wid = tid >> 5, lane = tid & 31;
    const int wm = wid & 1, woc = wid >> 1;
    const int g = lane >> 2, t = lane & 3;
    const int y0 = blockIdx.x, bb = blockIdx.y;

    if (tid == 0) { mbar_init(sbase, 1); mbar_init(sbase + 8, 1); }
    __syncthreads();
    if (tid == 0) {
        mbar_expect_tx(sbase, 32768);
        bulk_copy(sbase + SM_B, g_wU, 32768, sbase);
        mbar_expect_tx(sbase + 8, 32768);
        bulk_copy(sbase + SM_B + 32768, (const char*)g_wU + 32768, 32768, sbase + 8);
    }

    // T[u][tx 58][ic 128] fp32, stride 130 (column transform B^T d)
    float* T = (float*)(smem + SM_T);
    {
        const float* xb = x + (size_t)bb * 128 * HW;
        for (int it = 0; it < 16; it++) {
            int idx = it * 256 + tid;
            int tx = idx & 63, kp = idx >> 6;
            if (tx < 58) {
                int gx = tx - 1;
                float d[4][2];
#pragma unroll
                for (int dy = 0; dy < 4; dy++) {
                    int gy = 2 * y0 - 1 + dy;
                    bool ok = (unsigned)gy < 56u && (unsigned)gx < 56u;
                    const float* s = xb + (size_t)(2 * kp) * HW + gy * WW + gx;
                    d[dy][0] = ok ? s[0] : 0.f;
                    d[dy][1] = ok ? s[HW] : 0.f;
                }
                float2 t0 = {d[0][0] - d[2][0], d[0][1] - d[2][1]};
                float2 t1 = {d[1][0] + d[2][0], d[1][1] + d[2][1]};
                float2 t2 = {d[2][0] - d[1][0], d[2][1] - d[1][1]};
                float2 t3 = {d[1][0] - d[3][0], d[1][1] - d[3][1]};
                *(float2*)&T[(0 * 58 + tx) * 130 + 2 * kp] = t0;
                *(float2*)&T[(1 * 58 + tx) * 130 + 2 * kp] = t1;
                *(float2*)&T[(2 * 58 + tx) * 130 + 2 * kp] = t2;
                *(float2*)&T[(3 * 58 + tx) * 130 + 2 * kp] = t3;
            }
        }
    }
    // combine weights slice: cws[r][i][x] (x = 2b+j)
    float* cws = (float*)(smem + SM_CWS);
    for (int idx = tid; idx < 448; idx += 256) {
        int r = idx / 112, rem = idx % 112;
        cws[idx] = g_cw[r * HW + (2 * y0 + rem / 56) * 56 + rem % 56];
    }
    // zero A pad rows 28-31
    u32* Ab = (u32*)(smem + SM_A);
    for (int idx = 28 * 68 + tid; idx < 32 * 68; idx += 256) Ab[idx] = 0;
    __syncthreads();

    float acc[2][2][4][4];
#pragma unroll
    for (int i = 0; i < 2; i++)
#pragma unroll
        for (int j = 0; j < 2; j++)
#pragma unroll
            for (int nt = 0; nt < 4; nt++)
#pragma unroll
                for (int v2 = 0; v2 < 4; v2++) acc[i][j][nt][v2] = 0.f;

    buildA(Ab, T, 0, tid);
    __syncthreads();

    const int ar0 = (wm * 16 + g) * 68, ar1 = ar0 + 8 * 68;
    for (int s = 0; s < 64; s++) {
        const int e = s >> 2, r = s & 3, u = e >> 2, v = e & 3;
        mbar_wait(sbase + (s & 1) * 8, (s >> 1) & 1);

        float mf[4][4];
#pragma unroll
        for (int nt = 0; nt < 4; nt++)
#pragma unroll
            for (int v2 = 0; v2 < 4; v2++) mf[nt][v2] = 0.f;

        const u32* Bb = (const u32*)(smem + SM_B + (s & 1) * 32768);
#pragma unroll
        for (int ks = 0; ks < 8; ks++) {
            const int ak = ks * 8 + t;
            u32 a0 = Ab[ar0 + ak], a1 = Ab[ar1 + ak];
            u32 a2 = Ab[ar0 + ak + 4], a3 = Ab[ar1 + ak + 4];
#pragma unroll
            for (int nt = 0; nt < 4; nt++) {
                const int col = (woc * 32 + nt * 8 + g) ^ (t << 3);
                mma_f16(mf[nt][0], mf[nt][1], mf[nt][2], mf[nt][3],
                        a0, a1, a2, a3, Bb[ak * 128 + col], Bb[(ak + 4) * 128 + col]);
            }
        }
        // fold: acc[i][j] += A^T[i][u]*A^T[j][v]*cw_r(px) * mf
        const float cu0 = CAF[0][u], cu1 = CAF[1][u];
        const float cv0 = CAF[0][v], cv1 = CAF[1][v];
#pragma unroll
        for (int i = 0; i < 2; i++)
#pragma unroll
            for (int j = 0; j < 2; j++) {
                const float ca = (i ? cu1 : cu0) * (j ? cv1 : cv0);
                if (ca != 0.f) {
                    const float w0 = ca * cws[r * 112 + i * 56 + 2 * (wm * 16 + g) + j];
                    const float w1 = ca * cws[r * 112 + i * 56 + 2 * (wm * 16 + g + 8) + j];
#pragma unroll
                    for (int nt = 0; nt < 4; nt++) {
                        acc[i][j][nt][0] += w0 * mf[nt][0];
                        acc[i][j][nt][1] += w0 * mf[nt][1];
                        acc[i][j][nt][2] += w1 * mf[nt][2];
                        acc[i][j][nt][3] += w1 * mf[nt][3];
                    }
                }
            }
        __syncthreads();
        if (tid == 0 && s + 2 < 64) {
            const u32 mb = sbase + (s & 1) * 8;
            mbar_expect_tx(mb, 32768);
            bulk_copy(sbase + SM_B + (s & 1) * 32768,
                      (const char*)g_wU + (size_t)(s + 2) * 32768, 32768, mb);
        }
        if (r == 3 && e < 15) { buildA(Ab, T, e + 1, tid); __syncthreads(); }
    }

    // epilogue: direct stores + biases
    const float br0 = b_row[2 * y0], br1 = b_row[2 * y0 + 1];
#pragma unroll
    for (int i = 0; i < 2; i++)
#pragma unroll
        for (int j = 0; j < 2; j++)
#pragma unroll
            for (int nt = 0; nt < 4; nt++)
#pragma unroll
                for (int v2 = 0; v2 < 4; v2++) {
                    const int b = wm * 16 + g + 8 * (v2 >> 1);
                    if (b < 28) {
                        const int xx = 2 * b + j, yy = 2 * y0 + i;
                        const int oc = woc * 32 + nt * 8 + 2 * t + (v2 & 1);
                        out[((size_t)(bb * 128 + oc) * 56 + yy) * 56 + xx] =
                            acc[i][j][nt][v2] + (i ? br1 : br0) + b_col[xx] + b_ch[oc];
                    }
                }
}

extern "C" void kernel_launch(void* const* d_in, const int* in_sizes, int n_in,
                              void* d_out, int out_size) {
    const float* x      = (const float*)d_in[0];
    const float* w      = (const float*)d_in[1];
    const float* cw_row = (const float*)d_in[2];
    const float* cw_col = (const float*)d_in[3];
    const float* b_row  = (const float*)d_in[4];
    const float* b_col  = (const float*)d_in[5];
    const float* b_ch   = (const float*)d_in[6];
    float* out = (float*)d_out;

    cudaFuncSetAttribute(wino_kernel,
                         cudaFuncAttributeMaxDynamicSharedMemorySize, SM_TOTAL);
    prep_cw_kernel<<<(HW + 255) / 256, 256>>>(cw_row, cw_col);
    prep_wU_kernel<<<128, 256>>>(w);
    wino_kernel<<<dim3(28, 32), 256, SM_TOTAL>>>(x, out, b_row, b_col, b_ch);
}